// round 15
// baseline (speedup 1.0000x reference)
#include <cuda_runtime.h>
#include <cstdint>

// ---------------- problem constants ----------------
#define N      4096
#define NB     512
#define NSTEPS 64
#define DT     0.1f
#define OMDT   0.9f

#define TRAJ    ((size_t)(N + 2) * NB)
#define CONBASE ((size_t)NSTEPS * TRAJ)

// ---------------- GEMM tiling (int8, BK=64, BM=64) ----------------
#define BM 64
#define BN 64
#define BK 64
#define ROWB   80                       // 64 int8 + 16B pad (conflict-free)
#define MATA   (64 * ROWB)              // 5120
#define MATBB  (64 * ROWB)              // 5120
#define OFF_A1 0
#define OFF_A2 MATA
#define OFF_B1 (2 * MATA)
#define OFF_B2 (2 * MATA + MATBB)
#define STAGEB (2 * MATA + 2 * MATBB)   // 20480
#define HDR    2048
#define SMEMSZ (HDR + 3 * STAGEB)       // 63488 (x2 CTAs/SM = 127KB)
#define KSTEPS (N / BK)                 // 64
#define CSTRIDE 68

// ---------------- device scratch ----------------
__device__ float g_wf[(size_t)N * N];
__device__ unsigned g_wmax;
__device__ __align__(16) signed char g_W1[(size_t)N * N];
__device__ __align__(16) signed char g_W2[(size_t)N * N];
__device__ __align__(16) signed char g_h1[(size_t)NB * N];   // h^T split hi [b][k]
__device__ __align__(16) signed char g_h2[(size_t)NB * N];   // h^T split lo
__device__ float g_x[2][2 * NB];
__device__ float g_zp[128 * NB];                      // Z·h partials (32-row chunks)
__device__ float g_hmax[2][512];                      // per-CTA |h| partials, parity-buffered

// ---------------- helpers ----------------
__device__ __forceinline__ uint32_t s2u(const void* p) {
    uint32_t a;
    asm("{ .reg .u64 t; cvta.to.shared.u64 t, %1; cvt.u32.u64 %0, t; }" : "=r"(a) : "l"(p));
    return a;
}
__device__ __forceinline__ void cp16(uint32_t s, const void* g) {
    asm volatile("cp.async.cg.shared.global [%0], [%1], 16;" :: "r"(s), "l"(g));
}
#define CPCOMMIT() asm volatile("cp.async.commit_group;" ::: "memory")
#define CPWAIT1()  asm volatile("cp.async.wait_group 1;" ::: "memory")
#define CPWAIT0()  asm volatile("cp.async.wait_group 0;" ::: "memory")

#define IMMA(c, a0, a1, a2, a3, b0, b1) \
    asm volatile( \
        "mma.sync.aligned.m16n8k32.row.col.s32.s8.s8.s32 " \
        "{%0,%1,%2,%3},{%4,%5,%6,%7},{%8,%9},{%0,%1,%2,%3};" \
        : "+r"((c)[0]), "+r"((c)[1]), "+r"((c)[2]), "+r"((c)[3]) \
        : "r"(a0), "r"(a1), "r"(a2), "r"(a3), "r"(b0), "r"(b1))

#define LDSM4(r0, r1, r2, r3, a) \
    asm volatile("ldmatrix.sync.aligned.m8n8.x4.shared.b16 {%0,%1,%2,%3}, [%4];" \
                 : "=r"(r0), "=r"(r1), "=r"(r2), "=r"(r3) : "r"(a))

// ---------------- build: W' = Wp - 0.9 I, fp32 pass + absmax ----------------
__global__ void build1(const float* __restrict__ W, const float* __restrict__ Mv,
                       const float* __restrict__ Z, const float* __restrict__ U,
                       const float* __restrict__ V, const float* __restrict__ Bm,
                       const float* __restrict__ C)
{
    int j = blockIdx.x * 256 + threadIdx.x;
    int i = blockIdx.y;
    float cb = C[0] * Bm[0] + C[1] * Bm[1];
    float4 u = *reinterpret_cast<const float4*>(U + (size_t)i * 4);
    float4 v = *reinterpret_cast<const float4*>(V + (size_t)j * 4);
    float uv = u.x * v.x + u.y * v.y + u.z * v.z + u.w * v.w;
    float val = DT * W[(size_t)i * N + j] + cb * Mv[i] * Z[j] + DT * uv;  // NO diag
    g_wf[(size_t)i * N + j] = val;
    float a = fabsf(val);
#pragma unroll
    for (int o = 16; o; o >>= 1) a = fmaxf(a, __shfl_xor_sync(~0u, a, o));
    __shared__ float wmx[8];
    if ((threadIdx.x & 31) == 0) wmx[threadIdx.x >> 5] = a;
    __syncthreads();
    if (threadIdx.x == 0) {
        float m = wmx[0];
#pragma unroll
        for (int k = 1; k < 8; ++k) m = fmaxf(m, wmx[k]);
        atomicMax(&g_wmax, __float_as_uint(m));
    }
}

// ---------------- build: dual-int8 split of W' ----------------
__global__ void build2()
{
    int j = blockIdx.x * 256 + threadIdx.x;
    int i = blockIdx.y;
    float inv = 127.f / fmaxf(__uint_as_float(g_wmax), 1e-30f);
    float q = g_wf[(size_t)i * N + j] * inv;
    float q1 = rintf(q);
    float q2 = rintf(128.f * (q - q1));
    g_W1[(size_t)i * N + j] = (signed char)(int)q1;
    g_W2[(size_t)i * N + j] = (signed char)(int)q2;
}

// ---------------- init: traj_0 h rows ----------------
__global__ void init_traj0(const float* __restrict__ h0, float* __restrict__ out)
{
    size_t idx = (size_t)blockIdx.x * 1024 + threadIdx.x;
    out[2 * NB + idx] = h0[idx];
}

// ---------------- init: x copy + hmax[0] partials (512 partials) ----------------
__global__ void init_hx(const float* __restrict__ h0, const float* __restrict__ x0,
                        const float* __restrict__ x1)
{
    size_t base = (size_t)blockIdx.x * 4096;
    float a = 0.f;
#pragma unroll 8
    for (int k = 0; k < 32; ++k)
        a = fmaxf(a, fabsf(h0[base + threadIdx.x + k * 128]));
#pragma unroll
    for (int o = 16; o; o >>= 1) a = fmaxf(a, __shfl_xor_sync(~0u, a, o));
    __shared__ float mx[4];
    if ((threadIdx.x & 31) == 0) mx[threadIdx.x >> 5] = a;
    __syncthreads();
    if (threadIdx.x == 0)
        g_hmax[0][blockIdx.x] = fmaxf(fmaxf(mx[0], mx[1]), fmaxf(mx[2], mx[3]));
    if (blockIdx.x == 0)
        for (int k = threadIdx.x; k < NB; k += 128) {
            g_x[0][k]      = x0[k];
            g_x[0][NB + k] = x1[k];
        }
}

// ---------------- per-step quantize ----------------
// grid (128, 16), block (32, 8)
__global__ void quant(const float* __restrict__ hrows, const float* __restrict__ Zv, int par)
{
    __shared__ float tt[32][33];
    __shared__ float zsm[8][32];
    int tx = threadIdx.x, ty = threadIdx.y;
    int jb = blockIdx.x * 32, bb = blockIdx.y * 32;

    float mx = 1e-30f;
    const float4* hm = reinterpret_cast<const float4*>(g_hmax[par]);
#pragma unroll
    for (int k = 0; k < 128; ++k) {
        float4 v = hm[k];
        mx = fmaxf(mx, fmaxf(fmaxf(v.x, v.y), fmaxf(v.z, v.w)));
    }
    float inv = 127.f / mx;

    float zacc = 0.f;
#pragma unroll
    for (int r = 0; r < 4; ++r) {
        int j = jb + ty + r * 8;
        float v = hrows[(size_t)j * NB + bb + tx];
        tt[ty + r * 8][tx] = v;
        zacc += Zv[j] * v;
    }
    zsm[ty][tx] = zacc;
    __syncthreads();
    if (ty == 0) {
        float s = 0.f;
#pragma unroll
        for (int k = 0; k < 8; ++k) s += zsm[k][tx];
        g_zp[blockIdx.x * NB + bb + tx] = s;
    }
#pragma unroll
    for (int r = 0; r < 4; ++r) {
        int b = bb + ty + r * 8;
        int j = jb + tx;
        float q = tt[tx][ty + r * 8] * inv;
        float q1 = rintf(q);
        float q2 = rintf(128.f * (q - q1));
        g_h1[(size_t)b * N + j] = (signed char)(int)q1;
        g_h2[(size_t)b * N + j] = (signed char)(int)q2;
    }
}

// ---------------- final step outputs ----------------
__global__ void final_xcon(const float* __restrict__ Bm, float* __restrict__ out)
{
    int b = threadIdx.x;  // 512
    float zh = 0.f;
#pragma unroll
    for (int c = 0; c < 128; ++c) zh += g_zp[c * NB + b];
    const float* xc = g_x[1];
    out[(size_t)63 * TRAJ + b]      = xc[b];
    out[(size_t)63 * TRAJ + NB + b] = xc[NB + b];
    out[CONBASE + (size_t)63 * NB + b] = Bm[1] * zh;
}

// ---------------- fused step kernel: int8 IMMA, 32x32 warp tile ----------------
// h_next = sW·sh·(W1h1 + (W1h2 + W2h1)/128) + 0.9·h + M ⊗ cax
__global__ void __launch_bounds__(128, 2)
gemm_step(int cur, const float* __restrict__ Ain, const float* __restrict__ Bm,
          const float* __restrict__ Cin, const float* __restrict__ Mv,
          float* __restrict__ out, int t)
{
    extern __shared__ char smem[];
    const uint32_t sb = s2u(smem);
    const int tid = threadIdx.x;
    const int lane = tid & 31;
    const int wid = tid >> 5;
    const int wm = wid >> 1, wn = wid & 1;      // 2 x 2 warp grid, 32x32 tiles
    const int nt = blockIdx.x, mt = blockIdx.y; // (8, 64)
    const int m0 = mt * BM, b0t = nt * BN;
    const int par = t & 1;

    float* cax_s = reinterpret_cast<float*>(smem + 64);     // 64 floats
    float* m_s   = reinterpret_cast<float*>(smem + 640);    // 64 floats

    // sh = max|h_t| / 127 (uniform reduce of 512 partials)
    float hmx = 1e-30f;
    {
        const float4* hm = reinterpret_cast<const float4*>(g_hmax[par]);
#pragma unroll
        for (int k = 0; k < 128; ++k) {
            float4 v = hm[k];
            hmx = fmaxf(hmx, fmaxf(fmaxf(v.x, v.y), fmaxf(v.z, v.w)));
        }
    }
    const float sh = hmx / 127.f;

    // ---- prologue: cax; CTA(0,0) global x/con ----
    {
        const float* xc = g_x[cur];
        if (tid < 64) m_s[tid] = Mv[m0 + tid];
        if (tid >= 64) {
            float ca0 = Cin[0] * Ain[0] + Cin[1] * Ain[2];
            float ca1 = Cin[0] * Ain[1] + Cin[1] * Ain[3];
            int b = b0t + tid - 64;
            float zh = 0.f;
#pragma unroll
            for (int c = 0; c < 128; ++c) zh += g_zp[c * NB + b];
            cax_s[tid - 64] = DT * (ca0 * xc[b] + ca1 * xc[NB + b]);
        }
        if (mt == 0 && nt == 0) {
            float* xn = g_x[cur ^ 1];
            float a0 = Ain[0], a1 = Ain[1], a2 = Ain[2], a3 = Ain[3];
            float bm0 = Bm[0], bm1 = Bm[1];
#pragma unroll
            for (int k = 0; k < 4; ++k) {
                int bb = tid + k * 128;
                float z2 = 0.f;
#pragma unroll
                for (int c = 0; c < 128; ++c) z2 += g_zp[c * NB + bb];
                float y0 = xc[bb], y1 = xc[NB + bb];
                out[(size_t)t * TRAJ + bb]      = y0;
                out[(size_t)t * TRAJ + NB + bb] = y1;
                out[CONBASE + (size_t)t * NB + bb] = bm1 * z2;
                xn[bb]      = a0 * y0 + a1 * y1 + bm0 * z2;
                xn[NB + bb] = a2 * y0 + a3 * y1 + bm1 * z2;
            }
        }
    }
    __syncthreads();

    const signed char* gA1 = g_W1 + (size_t)m0 * N;
    const signed char* gA2 = g_W2 + (size_t)m0 * N;
    const signed char* gB1 = g_h1 + (size_t)b0t * N;
    const signed char* gB2 = g_h2 + (size_t)b0t * N;

    auto issue = [&](int ks) {
        int s = ks % 3;
        uint32_t stb = sb + HDR + s * STAGEB;
        size_t kb = (size_t)ks * BK;
        // 64 rows x 4 chunks = 256 cp16 per matrix, 2 per thread
#pragma unroll
        for (int it = 0; it < 2; ++it) {
            int idx = it * 128 + tid;
            int row = idx >> 2, chunk = idx & 3;
            uint32_t so = (uint32_t)(row * ROWB + chunk * 16);
            size_t go = (size_t)row * N + kb + chunk * 16;
            cp16(stb + OFF_A1 + so, gA1 + go);
            cp16(stb + OFF_A2 + so, gA2 + go);
            cp16(stb + OFF_B1 + so, gB1 + go);
            cp16(stb + OFF_B2 + so, gB2 + go);
        }
    };

    issue(0); CPCOMMIT();
    issue(1); CPCOMMIT();

    int accM[2][4][4], accC[2][4][4];
#pragma unroll
    for (int mi = 0; mi < 2; ++mi)
#pragma unroll
        for (int ni = 0; ni < 4; ++ni)
#pragma unroll
            for (int r = 0; r < 4; ++r) { accM[mi][ni][r] = 0; accC[mi][ni][r] = 0; }

    // ldmatrix offsets (byte-identical to bf16 m16n8k16 mapping)
    const int lr = lane & 7;
    const int g  = lane >> 3;
    const uint32_t aoff = (uint32_t)((wm * 32 + (g & 1) * 8 + lr) * ROWB + (g >> 1) * 16);
    const uint32_t boff = (uint32_t)((wn * 32 + (g >> 1) * 8 + lr) * ROWB + (g & 1) * 16);

    for (int ks = 0; ks < KSTEPS; ++ks) {
        CPWAIT1();
        __syncthreads();
        if (ks + 2 < KSTEPS) issue(ks + 2);
        CPCOMMIT();

        const uint32_t stb = sb + HDR + (ks % 3) * STAGEB;
        const uint32_t pA1 = stb + OFF_A1 + aoff;
        const uint32_t pA2 = stb + OFF_A2 + aoff;
        const uint32_t pB1 = stb + OFF_B1 + boff;
        const uint32_t pB2 = stb + OFF_B2 + boff;

#pragma unroll
        for (int kh = 0; kh < 2; ++kh) {
            const uint32_t khb = kh * 32;

            uint32_t b1[4][2], b2[4][2];
#pragma unroll
            for (int p = 0; p < 2; ++p) {
                LDSM4(b1[2*p][0], b1[2*p][1], b1[2*p+1][0], b1[2*p+1][1],
                      pB1 + p * (16 * ROWB) + khb);
                LDSM4(b2[2*p][0], b2[2*p][1], b2[2*p+1][0], b2[2*p+1][1],
                      pB2 + p * (16 * ROWB) + khb);
            }
            uint32_t a1[2][4], a2[2][4];
#pragma unroll
            for (int mi = 0; mi < 2; ++mi) {
                LDSM4(a1[mi][0], a1[mi][1], a1[mi][2], a1[mi][3],
                      pA1 + mi * (16 * ROWB) + khb);
                LDSM4(a2[mi][0], a2[mi][1], a2[mi][2], a2[mi][3],
                      pA2 + mi * (16 * ROWB) + khb);
            }

            // main: W1·h1 (8 IMMAs), then corr passes (8 + 8)
#pragma unroll
            for (int mi = 0; mi < 2; ++mi)
#pragma unroll
                for (int ni = 0; ni < 4; ++ni)
                    IMMA(accM[mi][ni], a1[mi][0], a1[mi][1], a1[mi][2], a1[mi][3],
                         b1[ni][0], b1[ni][1]);
#pragma unroll
            for (int mi = 0; mi < 2; ++mi)
#pragma unroll
                for (int ni = 0; ni < 4; ++ni)
                    IMMA(accC[mi][ni], a1[mi][0], a1[mi][1], a1[mi][2], a1[mi][3],
                         b2[ni][0], b2[ni][1]);
#pragma unroll
            for (int mi = 0; mi < 2; ++mi)
#pragma unroll
                for (int ni = 0; ni < 4; ++ni)
                    IMMA(accC[mi][ni], a2[mi][0], a2[mi][1], a2[mi][2], a2[mi][3],
                         b1[ni][0], b1[ni][1]);
        }
    }
    CPWAIT0();
    __syncthreads();

    // ---- epilogue Phase A: scale + diag + rank-1, into Cs; absmax partials ----
    float* Cs = reinterpret_cast<float*>(smem + HDR);
    const float scm = (__uint_as_float(g_wmax) / 127.f) * sh;
    const float scc = scm * (1.f / 128.f);
    const float* trajt = out + (size_t)t * TRAJ;
    float amax = 0.f;
#pragma unroll
    for (int mi = 0; mi < 2; ++mi) {
#pragma unroll
        for (int ni = 0; ni < 4; ++ni) {
            int row = wm * 32 + mi * 16 + (lane >> 2);
            int col = wn * 32 + ni * 8 + (lane & 3) * 2;
            const int* cm = accM[mi][ni];
            const int* cc = accC[mi][ni];
            float2 hA = *reinterpret_cast<const float2*>(
                trajt + (size_t)(2 + m0 + row) * NB + b0t + col);
            float2 hB = *reinterpret_cast<const float2*>(
                trajt + (size_t)(2 + m0 + row + 8) * NB + b0t + col);
            float v0 = scm * (float)cm[0] + scc * (float)cc[0] + m_s[row] * cax_s[col]     + OMDT * hA.x;
            float v1 = scm * (float)cm[1] + scc * (float)cc[1] + m_s[row] * cax_s[col + 1] + OMDT * hA.y;
            float v2 = scm * (float)cm[2] + scc * (float)cc[2] + m_s[row + 8] * cax_s[col]     + OMDT * hB.x;
            float v3 = scm * (float)cm[3] + scc * (float)cc[3] + m_s[row + 8] * cax_s[col + 1] + OMDT * hB.y;
            amax = fmaxf(amax, fmaxf(fmaxf(fabsf(v0), fabsf(v1)), fmaxf(fabsf(v2), fabsf(v3))));
            *reinterpret_cast<float2*>(&Cs[row * CSTRIDE + col]) = make_float2(v0, v1);
            *reinterpret_cast<float2*>(&Cs[(row + 8) * CSTRIDE + col]) = make_float2(v2, v3);
        }
    }
#pragma unroll
    for (int o = 16; o; o >>= 1) amax = fmaxf(amax, __shfl_xor_sync(~0u, amax, o));
    float* wred = reinterpret_cast<float*>(smem + 1792);
    if (lane == 0) wred[wid] = amax;
    __syncthreads();
    if (tid == 0)
        g_hmax[par ^ 1][mt * 8 + nt] =
            fmaxf(fmaxf(wred[0], wred[1]), fmaxf(wred[2], wred[3]));

    // ---- Phase B: traj_{t+1} h rows (64 rows, 2 threads per row) ----
    {
        int row = tid >> 1;
        int cb = (tid & 1) * 32;
        const float* src = Cs + row * CSTRIDE + cb;
        float* dst = out + (size_t)(t + 1) * TRAJ + (size_t)(2 + m0 + row) * NB + b0t + cb;
#pragma unroll
        for (int j2 = 0; j2 < 32; j2 += 4)
            *reinterpret_cast<float4*>(dst + j2) =
                *reinterpret_cast<const float4*>(src + j2);
    }
}

// ---------------- launch ----------------
extern "C" void kernel_launch(void* const* d_in, const int* in_sizes, int n_in,
                              void* d_out, int out_size)
{
    const float* x0 = (const float*)d_in[0];
    const float* x1 = (const float*)d_in[1];
    const float* h0 = (const float*)d_in[2];
    const float* A  = (const float*)d_in[3];
    const float* Bm = (const float*)d_in[4];
    const float* C  = (const float*)d_in[5];
    const float* M  = (const float*)d_in[6];
    const float* Z  = (const float*)d_in[7];
    const float* U  = (const float*)d_in[8];
    const float* V  = (const float*)d_in[9];
    const float* W  = (const float*)d_in[10];
    (void)in_sizes; (void)n_in; (void)out_size;
    float* out = (float*)d_out;

    cudaFuncSetAttribute(gemm_step, cudaFuncAttributeMaxDynamicSharedMemorySize, SMEMSZ);

    build1<<<dim3(N / 256, N), 256>>>(W, M, Z, U, V, Bm, C);
    build2<<<dim3(N / 256, N), 256>>>();
    init_traj0<<<(N * NB) / 1024, 1024>>>(h0, out);
    init_hx<<<512, 128>>>(h0, x0, x1);

    for (int t = 0; t < NSTEPS - 1; ++t) {
        quant<<<dim3(128, 16), dim3(32, 8)>>>(out + (size_t)t * TRAJ + 2 * NB, Z, t & 1);
        gemm_step<<<dim3(NB / BN, N / BM), 128, SMEMSZ>>>(t & 1, A, Bm, C, M, out, t);
    }
    quant<<<dim3(128, 16), dim3(32, 8)>>>(out + (size_t)63 * TRAJ + 2 * NB, Z, 1);
    final_xcon<<<1, 512>>>(Bm, out);
}

// round 16
// speedup vs baseline: 1.6264x; 1.6264x over previous
#include <cuda_runtime.h>
#include <cuda_fp16.h>
#include <cstdint>

// ---------------- problem constants ----------------
#define N      4096
#define NB     512
#define NSTEPS 64
#define DT     0.1f
#define OMDT   0.9f
#define SLO    1024.0f
#define INVSLO (1.0f / 1024.0f)

#define TRAJ    ((size_t)(N + 2) * NB)
#define CONBASE ((size_t)NSTEPS * TRAJ)

// ---------------- GEMM tiling ----------------
#define BM 128
#define BN 64
#define BK 32
#define STAGES 3
#define ROWB   80                       // padded row: 32 fp16 + 16B pad
#define MATA   (128 * ROWB)             // 10240
#define MATBB  (64 * ROWB)              // 5120
#define OFF_AH 0
#define OFF_AL MATA
#define OFF_BH (2 * MATA)
#define OFF_BL (2 * MATA + MATBB)
#define STAGEB (2 * MATA + 2 * MATBB)   // 30720
#define HDR    2048
#define SMEMSZ (HDR + STAGES * STAGEB)  // 94208 (x2 CTAs/SM)
#define KSTEPS (N / BK)                 // 128
#define CSTRIDE 68

// ---------------- device scratch ----------------
__device__ __align__(256) __half g_Wh[(size_t)N * N];
__device__ __align__(256) __half g_Wl[(size_t)N * N];     // (W'-Wh)*1024
__device__ __align__(256) __half g_hh[2][(size_t)NB * N]; // h^T hi [b][k]
__device__ __align__(256) __half g_hl[2][(size_t)NB * N]; // (h-hh)*1024
__device__ float g_x[2][2 * NB];
__device__ float g_zp[2][64 * NB];       // Z·h partials (64-row chunks)

// ---------------- helpers ----------------
__device__ __forceinline__ uint32_t s2u(const void* p) {
    uint32_t a;
    asm("{ .reg .u64 t; cvta.to.shared.u64 t, %1; cvt.u32.u64 %0, t; }" : "=r"(a) : "l"(p));
    return a;
}
__device__ __forceinline__ void cp16(uint32_t s, const void* g) {
    asm volatile("cp.async.cg.shared.global [%0], [%1], 16;" :: "r"(s), "l"(g));
}
#define CPCOMMIT() asm volatile("cp.async.commit_group;" ::: "memory")
#define CPWAIT1()  asm volatile("cp.async.wait_group 1;" ::: "memory")
#define CPWAIT0()  asm volatile("cp.async.wait_group 0;" ::: "memory")

// main product: fp16 inputs, f32 accumulate
#define MMAF32(c, a0, a1, a2, a3, b0, b1) \
    asm volatile( \
        "mma.sync.aligned.m16n8k16.row.col.f32.f16.f16.f32 " \
        "{%0,%1,%2,%3},{%4,%5,%6,%7},{%8,%9},{%0,%1,%2,%3};" \
        : "+f"((c)[0]), "+f"((c)[1]), "+f"((c)[2]), "+f"((c)[3]) \
        : "r"(a0), "r"(a1), "r"(a2), "r"(a3), "r"(b0), "r"(b1))

// correction products: fp16 inputs, f16 accumulate (2x rate hypothesis)
#define MMAF16(d, a0, a1, a2, a3, b0, b1) \
    asm volatile( \
        "mma.sync.aligned.m16n8k16.row.col.f16.f16.f16.f16 " \
        "{%0,%1},{%2,%3,%4,%5},{%6,%7},{%0,%1};" \
        : "+r"((d)[0]), "+r"((d)[1]) \
        : "r"(a0), "r"(a1), "r"(a2), "r"(a3), "r"(b0), "r"(b1))

#define LDSM4(r0, r1, r2, r3, a) \
    asm volatile("ldmatrix.sync.aligned.m8n8.x4.shared.b16 {%0,%1,%2,%3}, [%4];" \
                 : "=r"(r0), "=r"(r1), "=r"(r2), "=r"(r3) : "r"(a))

// ---------------- one-time build kernels ----------------
__global__ void build_wp(const float* __restrict__ W, const float* __restrict__ Mv,
                         const float* __restrict__ Z, const float* __restrict__ U,
                         const float* __restrict__ V, const float* __restrict__ Bm,
                         const float* __restrict__ C)
{
    int j = blockIdx.x * 256 + threadIdx.x;
    int i = blockIdx.y;
    float cb = C[0] * Bm[0] + C[1] * Bm[1];
    float4 u = *reinterpret_cast<const float4*>(U + (size_t)i * 4);
    float4 v = *reinterpret_cast<const float4*>(V + (size_t)j * 4);
    float uv = u.x * v.x + u.y * v.y + u.z * v.z + u.w * v.w;
    float val = DT * W[(size_t)i * N + j] + cb * Mv[i] * Z[j] + DT * uv;
    if (i == j) val += OMDT;
    __half hi = __float2half(val);
    float lo = (val - __half2float(hi)) * SLO;
    size_t a = (size_t)i * N + j;
    g_Wh[a] = hi;
    g_Wl[a] = __float2half(lo);
}

__global__ void init_h(const float* __restrict__ h0, float* __restrict__ out)
{
    __shared__ float t[32][33];
    int jb = blockIdx.x * 32, bb = blockIdx.y * 32;
    int tx = threadIdx.x, ty = threadIdx.y;  // 32 x 8
#pragma unroll
    for (int r = 0; r < 4; ++r) {
        int j = jb + ty + r * 8;
        float v = h0[(size_t)j * NB + bb + tx];
        t[ty + r * 8][tx] = v;
        out[(size_t)(2 + j) * NB + bb + tx] = v;
    }
    __syncthreads();
#pragma unroll
    for (int r = 0; r < 4; ++r) {
        int b = bb + ty + r * 8;
        int j = jb + tx;
        float v = t[tx][ty + r * 8];
        __half hi = __float2half(v);
        size_t a = (size_t)b * N + j;
        g_hh[0][a] = hi;
        g_hl[0][a] = __float2half((v - __half2float(hi)) * SLO);
    }
}

__global__ void init_zx(const float* __restrict__ h0, const float* __restrict__ Z,
                        const float* __restrict__ x0, const float* __restrict__ x1)
{
    int b = blockIdx.y * 128 + threadIdx.x;
    int j0 = blockIdx.x * 64;
    float s = 0.0f;
#pragma unroll 8
    for (int jj = 0; jj < 64; ++jj)
        s += Z[j0 + jj] * h0[(size_t)(j0 + jj) * NB + b];
    g_zp[0][blockIdx.x * NB + b] = s;
    if (blockIdx.x == 0 && blockIdx.y == 0) {
        for (int bb = threadIdx.x; bb < NB; bb += 128) {
            g_x[0][bb]      = x0[bb];
            g_x[0][NB + bb] = x1[bb];
        }
    }
}

__global__ void final_xcon(const float* __restrict__ Bm, float* __restrict__ out)
{
    int b = threadIdx.x;  // 512
    float zh = 0.0f;
#pragma unroll
    for (int c = 0; c < 64; ++c) zh += g_zp[1][c * NB + b];
    const float* xc = g_x[1];
    out[(size_t)63 * TRAJ + b]      = xc[b];
    out[(size_t)63 * TRAJ + NB + b] = xc[NB + b];
    out[CONBASE + (size_t)63 * NB + b] = Bm[1] * zh;
}

// ---------------- fused step kernel ----------------
// h_next = Wh·hh + (Wh·hl + Wl·hh)/1024 + M ⊗ cax
// main in f32-accum HMMA; both cross terms share one f16-accum set.
__global__ void __launch_bounds__(128, 2)
gemm_step(int cur, const float* __restrict__ Ain, const float* __restrict__ Bm,
          const float* __restrict__ Cin, const float* __restrict__ Mv,
          const float* __restrict__ Zv, float* __restrict__ out, int t)
{
    extern __shared__ char smem[];
    const uint32_t sb = s2u(smem);
    const int tid = threadIdx.x;
    const int lane = tid & 31;
    const int wid = tid >> 5;
    const int wm = wid >> 1, wn = wid & 1;      // 2 x 2 warp grid, 64x32 tiles
    const int nt = blockIdx.x, mt = blockIdx.y; // (8, 32)
    const int m0 = mt * BM, b0t = nt * BN;
    const int nxt = cur ^ 1;

    const __half* __restrict__ hh = g_hh[cur];
    const __half* __restrict__ hl = g_hl[cur];
    __half* __restrict__ oh = g_hh[nxt];
    __half* __restrict__ ol = g_hl[nxt];

    float* cax_s = reinterpret_cast<float*>(smem + 64);     // 64 floats
    float* m_s   = reinterpret_cast<float*>(smem + 640);    // 128 floats
    float* z_s   = reinterpret_cast<float*>(smem + 1216);   // 128 floats

    // ---- prologue: cax; m/z row caches; CTA(0,0) global x/con ----
    {
        const float* zp = g_zp[cur];
        const float* xc = g_x[cur];
        m_s[tid] = Mv[m0 + tid];
        z_s[tid] = Zv[m0 + tid];
        if (tid < 64) {
            float ca0 = Cin[0] * Ain[0] + Cin[1] * Ain[2];
            float ca1 = Cin[0] * Ain[1] + Cin[1] * Ain[3];
            int b = b0t + tid;
            float zh = 0.0f;
#pragma unroll
            for (int c = 0; c < 64; ++c) zh += zp[c * NB + b];
            cax_s[tid] = DT * (ca0 * xc[b] + ca1 * xc[NB + b]);
        }
        if (mt == 0 && nt == 0) {
            float* xn = g_x[nxt];
            float a0 = Ain[0], a1 = Ain[1], a2 = Ain[2], a3 = Ain[3];
            float bm0 = Bm[0], bm1 = Bm[1];
#pragma unroll
            for (int k = 0; k < 4; ++k) {
                int bb = tid + k * 128;
                float z2 = 0.0f;
#pragma unroll
                for (int c = 0; c < 64; ++c) z2 += zp[c * NB + bb];
                float y0 = xc[bb], y1 = xc[NB + bb];
                out[(size_t)t * TRAJ + bb]      = y0;
                out[(size_t)t * TRAJ + NB + bb] = y1;
                out[CONBASE + (size_t)t * NB + bb] = bm1 * z2;
                xn[bb]      = a0 * y0 + a1 * y1 + bm0 * z2;
                xn[NB + bb] = a2 * y0 + a3 * y1 + bm1 * z2;
            }
        }
    }
    __syncthreads();

    const char* gAh = (const char*)(g_Wh + (size_t)m0 * N);
    const char* gAl = (const char*)(g_Wl + (size_t)m0 * N);
    const char* gBh = (const char*)(hh + (size_t)b0t * N);
    const char* gBl = (const char*)(hl + (size_t)b0t * N);

    auto issue = [&](int ks) {
        int s = ks % STAGES;
        uint32_t stb = sb + HDR + s * STAGEB;
        size_t kb = (size_t)ks * (BK * 2);
        // A tiles: 128 rows x 4 chunks, 4 per thread per tile
#pragma unroll
        for (int it = 0; it < 4; ++it) {
            int idx = it * 128 + tid;
            int row = idx >> 2, chunk = idx & 3;
            uint32_t so = (uint32_t)(row * ROWB + chunk * 16);
            size_t go = (size_t)row * (N * 2) + kb + chunk * 16;
            cp16(stb + OFF_AH + so, gAh + go);
            cp16(stb + OFF_AL + so, gAl + go);
        }
        // B tiles: 64 rows x 4 chunks, 2 per thread per tile
#pragma unroll
        for (int it = 0; it < 2; ++it) {
            int idx = it * 128 + tid;
            int row = idx >> 2, chunk = idx & 3;
            uint32_t so = (uint32_t)(row * ROWB + chunk * 16);
            size_t go = (size_t)row * (N * 2) + kb + chunk * 16;
            cp16(stb + OFF_BH + so, gBh + go);
            cp16(stb + OFF_BL + so, gBl + go);
        }
    };

    issue(0); CPCOMMIT();
    issue(1); CPCOMMIT();

    float accM[4][4][4];
    uint32_t accC[4][4][2];   // f16x2 pairs, shared by both cross products
#pragma unroll
    for (int mi = 0; mi < 4; ++mi)
#pragma unroll
        for (int ni = 0; ni < 4; ++ni) {
#pragma unroll
            for (int r = 0; r < 4; ++r) accM[mi][ni][r] = 0.0f;
            accC[mi][ni][0] = 0u; accC[mi][ni][1] = 0u;
        }

    // ldmatrix lane-address offsets
    const int lr = lane & 7;
    const int g  = lane >> 3;
    const uint32_t aoff = (uint32_t)((wm * 64 + (g & 1) * 8 + lr) * ROWB + (g >> 1) * 16);
    const uint32_t boff = (uint32_t)((wn * 32 + (g >> 1) * 8 + lr) * ROWB + (g & 1) * 16);

    for (int ks = 0; ks < KSTEPS; ++ks) {
        CPWAIT1();
        __syncthreads();
        if (ks + 2 < KSTEPS) issue(ks + 2);
        CPCOMMIT();

        const uint32_t stb = sb + HDR + (ks % STAGES) * STAGEB;
        const uint32_t pAh = stb + OFF_AH + aoff;
        const uint32_t pAl = stb + OFF_AL + aoff;
        const uint32_t pBh = stb + OFF_BH + boff;
        const uint32_t pBl = stb + OFF_BL + boff;

#pragma unroll
        for (int kh = 0; kh < 2; ++kh) {
            const uint32_t khb = kh * 32;

            uint32_t bh[4][2], bl[4][2];
#pragma unroll
            for (int p = 0; p < 2; ++p) {
                LDSM4(bh[2*p][0], bh[2*p][1], bh[2*p+1][0], bh[2*p+1][1],
                      pBh + p * (16 * ROWB) + khb);
                LDSM4(bl[2*p][0], bl[2*p][1], bl[2*p+1][0], bl[2*p+1][1],
                      pBl + p * (16 * ROWB) + khb);
            }
            uint32_t ah[4][4], al[4][4];
#pragma unroll
            for (int mi = 0; mi < 4; ++mi) {
                LDSM4(ah[mi][0], ah[mi][1], ah[mi][2], ah[mi][3],
                      pAh + mi * (16 * ROWB) + khb);
                LDSM4(al[mi][0], al[mi][1], al[mi][2], al[mi][3],
                      pAl + mi * (16 * ROWB) + khb);
            }

            // main: Wh·hh  (f32 accumulate)
#pragma unroll
            for (int mi = 0; mi < 4; ++mi)
#pragma unroll
                for (int ni = 0; ni < 4; ++ni)
                    MMAF32(accM[mi][ni], ah[mi][0], ah[mi][1], ah[mi][2], ah[mi][3],
                           bh[ni][0], bh[ni][1]);
            // corr: Wh·hl  (f16 accumulate)
#pragma unroll
            for (int mi = 0; mi < 4; ++mi)
#pragma unroll
                for (int ni = 0; ni < 4; ++ni)
                    MMAF16(accC[mi][ni], ah[mi][0], ah[mi][1], ah[mi][2], ah[mi][3],
                           bl[ni][0], bl[ni][1]);
            // corr: Wl·hh  (f16 accumulate, same accumulators)
#pragma unroll
            for (int mi = 0; mi < 4; ++mi)
#pragma unroll
                for (int ni = 0; ni < 4; ++ni)
                    MMAF16(accC[mi][ni], al[mi][0], al[mi][1], al[mi][2], al[mi][3],
                           bh[ni][0], bh[ni][1]);
        }
    }
    CPWAIT0();
    __syncthreads();   // all compute done before Cs overwrites stage buffers

    // ---- Phase A: combine main + corr/1024 + M[i]*cax[b] -> Cs ----
    float* Cs = reinterpret_cast<float*>(smem + HDR);
#pragma unroll
    for (int mi = 0; mi < 4; ++mi) {
#pragma unroll
        for (int ni = 0; ni < 4; ++ni) {
            int row = wm * 64 + mi * 16 + (lane >> 2);
            int col = wn * 32 + ni * 8 + (lane & 3) * 2;
            float* c = accM[mi][ni];
            float2 c01 = __half22float2(*reinterpret_cast<__half2*>(&accC[mi][ni][0]));
            float2 c23 = __half22float2(*reinterpret_cast<__half2*>(&accC[mi][ni][1]));
            float2 v0 = make_float2(c[0] + c01.x * INVSLO + m_s[row] * cax_s[col],
                                    c[1] + c01.y * INVSLO + m_s[row] * cax_s[col + 1]);
            float2 v1 = make_float2(c[2] + c23.x * INVSLO + m_s[row + 8] * cax_s[col],
                                    c[3] + c23.y * INVSLO + m_s[row + 8] * cax_s[col + 1]);
            *reinterpret_cast<float2*>(&Cs[row * CSTRIDE + col]) = v0;
            *reinterpret_cast<float2*>(&Cs[(row + 8) * CSTRIDE + col]) = v1;
        }
    }
    __syncthreads();

    // ---- Phase B: traj_{t+1} h rows (one row of 64 floats per thread) ----
    {
        int row = tid;
        const float* src = Cs + row * CSTRIDE;
        float* dst = out + (size_t)(t + 1) * TRAJ + (size_t)(2 + m0 + row) * NB + b0t;
#pragma unroll
        for (int j = 0; j < 64; j += 4)
            *reinterpret_cast<float4*>(dst + j) = *reinterpret_cast<const float4*>(src + j);
    }

    // ---- Phase C: transposed fp16 split + Z·h partials ----
    {
        int b = tid >> 1;
        int rb = (tid & 1) * 64;
        size_t base = (size_t)(b0t + b) * N + m0 + rb;
        uint32_t* ohp = reinterpret_cast<uint32_t*>(oh + base);
        uint32_t* olp = reinterpret_cast<uint32_t*>(ol + base);
        float zh = 0.0f;
#pragma unroll
        for (int r = 0; r < 64; r += 2) {
            float v0 = Cs[(rb + r) * CSTRIDE + b];
            float v1 = Cs[(rb + r + 1) * CSTRIDE + b];
            zh += z_s[rb + r] * v0 + z_s[rb + r + 1] * v1;
            __half h0 = __float2half(v0);
            __half h1 = __float2half(v1);
            __half l0 = __float2half((v0 - __half2float(h0)) * SLO);
            __half l1 = __float2half((v1 - __half2float(h1)) * SLO);
            ohp[r >> 1] = (uint32_t)__half_as_ushort(h0)
                        | ((uint32_t)__half_as_ushort(h1) << 16);
            olp[r >> 1] = (uint32_t)__half_as_ushort(l0)
                        | ((uint32_t)__half_as_ushort(l1) << 16);
        }
        g_zp[nxt][(mt * 2 + (tid & 1)) * NB + b0t + b] = zh;
    }
}

// ---------------- launch ----------------
extern "C" void kernel_launch(void* const* d_in, const int* in_sizes, int n_in,
                              void* d_out, int out_size)
{
    const float* x0 = (const float*)d_in[0];
    const float* x1 = (const float*)d_in[1];
    const float* h0 = (const float*)d_in[2];
    const float* A  = (const float*)d_in[3];
    const float* Bm = (const float*)d_in[4];
    const float* C  = (const float*)d_in[5];
    const float* M  = (const float*)d_in[6];
    const float* Z  = (const float*)d_in[7];
    const float* U  = (const float*)d_in[8];
    const float* V  = (const float*)d_in[9];
    const float* W  = (const float*)d_in[10];
    (void)in_sizes; (void)n_in; (void)out_size;
    float* out = (float*)d_out;

    cudaFuncSetAttribute(gemm_step, cudaFuncAttributeMaxDynamicSharedMemorySize, SMEMSZ);

    build_wp<<<dim3(N / 256, N), 256>>>(W, M, Z, U, V, Bm, C);
    init_h<<<dim3(N / 32, NB / 32), dim3(32, 8)>>>(h0, out);
    init_zx<<<dim3(64, 4), 128>>>(h0, Z, x0, x1);

    for (int t = 0; t < NSTEPS - 1; ++t)
        gemm_step<<<dim3(NB / BN, N / BM), 128, SMEMSZ>>>(t & 1, A, Bm, C, M, Z, out, t);

    final_xcon<<<1, 512>>>(Bm, out);
}

// round 17
// speedup vs baseline: 2.5286x; 1.5547x over previous
#include <cuda_runtime.h>
#include <cuda_fp16.h>
#include <cstdint>

// ---------------- problem constants ----------------
#define N      4096
#define NB     512
#define NSTEPS 64
#define DT     0.1f
#define OMDT   0.9f

#define TRAJ    ((size_t)(N + 2) * NB)
#define CONBASE ((size_t)NSTEPS * TRAJ)

// ---------------- GEMM tiling ----------------
#define BM 128
#define BN 64
#define BK 32
#define STAGES 3
#define ROWB   80                       // padded row: 32 fp16 + 16B pad (conflict-free)
#define MATA   (128 * ROWB)             // 10240
#define MATBB  (64 * ROWB)              // 5120
#define OFF_AH 0
#define OFF_AL MATA
#define OFF_BH (2 * MATA)
#define OFF_BL (2 * MATA + MATBB)
#define STAGEB (2 * MATA + 2 * MATBB)   // 30720
#define HDR    2048
#define SMEMSZ (HDR + STAGES * STAGEB)  // 94208 (x2 CTAs/SM = 188KB)
#define KSTEPS (N / BK)                 // 128
#define CSTRIDE 68

// ---------------- device scratch ----------------
__device__ __align__(256) __half g_Wh[(size_t)N * N];
__device__ __align__(256) __half g_Wl[(size_t)N * N];     // W' - Wh (unscaled)
__device__ __align__(256) __half g_hh[2][(size_t)NB * N]; // h^T hi [b][k]
__device__ __align__(256) __half g_hl[2][(size_t)NB * N]; // h - hh (unscaled)
__device__ float g_x[2][2 * NB];
__device__ float g_zp[2][128 * NB];      // Z·h partials (32-row chunks)

// ---------------- helpers ----------------
__device__ __forceinline__ uint32_t s2u(const void* p) {
    uint32_t a;
    asm("{ .reg .u64 t; cvta.to.shared.u64 t, %1; cvt.u32.u64 %0, t; }" : "=r"(a) : "l"(p));
    return a;
}
__device__ __forceinline__ void cp16(uint32_t s, const void* g) {
    asm volatile("cp.async.cg.shared.global [%0], [%1], 16;" :: "r"(s), "l"(g));
}
#define CPCOMMIT() asm volatile("cp.async.commit_group;" ::: "memory")
#define CPWAIT1()  asm volatile("cp.async.wait_group 1;" ::: "memory")
#define CPWAIT0()  asm volatile("cp.async.wait_group 0;" ::: "memory")

#define MMA(c, a0, a1, a2, a3, b0, b1) \
    asm volatile( \
        "mma.sync.aligned.m16n8k16.row.col.f32.f16.f16.f32 " \
        "{%0,%1,%2,%3},{%4,%5,%6,%7},{%8,%9},{%0,%1,%2,%3};" \
        : "+f"((c)[0]), "+f"((c)[1]), "+f"((c)[2]), "+f"((c)[3]) \
        : "r"(a0), "r"(a1), "r"(a2), "r"(a3), "r"(b0), "r"(b1))

#define LDSM4(r0, r1, r2, r3, a) \
    asm volatile("ldmatrix.sync.aligned.m8n8.x4.shared.b16 {%0,%1,%2,%3}, [%4];" \
                 : "=r"(r0), "=r"(r1), "=r"(r2), "=r"(r3) : "r"(a))

// ---------------- one-time build kernels ----------------
__global__ void build_wp(const float* __restrict__ W, const float* __restrict__ Mv,
                         const float* __restrict__ Z, const float* __restrict__ U,
                         const float* __restrict__ V, const float* __restrict__ Bm,
                         const float* __restrict__ C)
{
    int j = blockIdx.x * 256 + threadIdx.x;
    int i = blockIdx.y;
    float cb = C[0] * Bm[0] + C[1] * Bm[1];
    float4 u = *reinterpret_cast<const float4*>(U + (size_t)i * 4);
    float4 v = *reinterpret_cast<const float4*>(V + (size_t)j * 4);
    float uv = u.x * v.x + u.y * v.y + u.z * v.z + u.w * v.w;
    float val = DT * W[(size_t)i * N + j] + cb * Mv[i] * Z[j] + DT * uv;
    if (i == j) val += OMDT;
    __half hi = __float2half(val);
    size_t a = (size_t)i * N + j;
    g_Wh[a] = hi;
    g_Wl[a] = __float2half(val - __half2float(hi));
}

__global__ void init_h(const float* __restrict__ h0, float* __restrict__ out)
{
    __shared__ float t[32][33];
    int jb = blockIdx.x * 32, bb = blockIdx.y * 32;
    int tx = threadIdx.x, ty = threadIdx.y;  // 32 x 8
#pragma unroll
    for (int r = 0; r < 4; ++r) {
        int j = jb + ty + r * 8;
        float v = h0[(size_t)j * NB + bb + tx];
        t[ty + r * 8][tx] = v;
        out[(size_t)(2 + j) * NB + bb + tx] = v;
    }
    __syncthreads();
#pragma unroll
    for (int r = 0; r < 4; ++r) {
        int b = bb + ty + r * 8;
        int j = jb + tx;
        float v = t[tx][ty + r * 8];
        __half hi = __float2half(v);
        size_t a = (size_t)b * N + j;
        g_hh[0][a] = hi;
        g_hl[0][a] = __float2half(v - __half2float(hi));
    }
}

__global__ void init_zx(const float* __restrict__ h0, const float* __restrict__ Z,
                        const float* __restrict__ x0, const float* __restrict__ x1)
{
    int b = blockIdx.y * 128 + threadIdx.x;
    int j0 = blockIdx.x * 32;
    float s = 0.0f;
#pragma unroll 8
    for (int jj = 0; jj < 32; ++jj)
        s += Z[j0 + jj] * h0[(size_t)(j0 + jj) * NB + b];
    g_zp[0][blockIdx.x * NB + b] = s;
    if (blockIdx.x == 0 && blockIdx.y == 0) {
        for (int bb = threadIdx.x; bb < NB; bb += 128) {
            g_x[0][bb]      = x0[bb];
            g_x[0][NB + bb] = x1[bb];
        }
    }
}

__global__ void final_xcon(const float* __restrict__ Bm, float* __restrict__ out)
{
    int b = threadIdx.x;  // 512
    float zh = 0.0f;
#pragma unroll
    for (int c = 0; c < 128; ++c) zh += g_zp[1][c * NB + b];
    const float* xc = g_x[1];
    out[(size_t)63 * TRAJ + b]      = xc[b];
    out[(size_t)63 * TRAJ + NB + b] = xc[NB + b];
    out[CONBASE + (size_t)63 * NB + b] = Bm[1] * zh;
}

// ---------------- fused step kernel ----------------
// h_next = Wh·hh + Wh·hl + Wl·hh + M ⊗ cax   (fp16 splits, all f32-acc, one acc set)
// 256 threads, 4x2 warp grid, 32x32 warp tile, 2 CTAs/SM -> 4 warps/SMSP.
__global__ void __launch_bounds__(256, 2)
gemm_step(int cur, const float* __restrict__ Ain, const float* __restrict__ Bm,
          const float* __restrict__ Cin, const float* __restrict__ Mv,
          const float* __restrict__ Zv, float* __restrict__ out, int t)
{
    extern __shared__ char smem[];
    const uint32_t sb = s2u(smem);
    const int tid = threadIdx.x;
    const int lane = tid & 31;
    const int wid = tid >> 5;
    const int wm = wid >> 1, wn = wid & 1;      // 4 x 2 warp grid
    const int nt = blockIdx.x, mt = blockIdx.y; // (8, 32)
    const int m0 = mt * BM, b0t = nt * BN;
    const int nxt = cur ^ 1;

    const __half* __restrict__ hh = g_hh[cur];
    const __half* __restrict__ hl = g_hl[cur];
    __half* __restrict__ oh = g_hh[nxt];
    __half* __restrict__ ol = g_hl[nxt];

    float* cax_s = reinterpret_cast<float*>(smem + 64);     // 64 floats
    float* m_s   = reinterpret_cast<float*>(smem + 640);    // 128 floats
    float* z_s   = reinterpret_cast<float*>(smem + 1216);   // 128 floats

    // ---- prologue ----
    {
        const float* zp = g_zp[cur];
        const float* xc = g_x[cur];
        if (tid < 128) {
            m_s[tid] = Mv[m0 + tid];
            z_s[tid] = Zv[m0 + tid];
        } else if (tid < 192) {
            float ca0 = Cin[0] * Ain[0] + Cin[1] * Ain[2];
            float ca1 = Cin[0] * Ain[1] + Cin[1] * Ain[3];
            int b = b0t + tid - 128;
            float zh = 0.0f;
#pragma unroll
            for (int c = 0; c < 128; ++c) zh += zp[c * NB + b];
            cax_s[tid - 128] = DT * (ca0 * xc[b] + ca1 * xc[NB + b]);
        }
        if (mt == 0 && nt == 0) {
            float* xn = g_x[nxt];
            float a0 = Ain[0], a1 = Ain[1], a2 = Ain[2], a3 = Ain[3];
            float bm0 = Bm[0], bm1 = Bm[1];
#pragma unroll
            for (int k = 0; k < 2; ++k) {
                int bb = tid + k * 256;
                float z2 = 0.0f;
#pragma unroll
                for (int c = 0; c < 128; ++c) z2 += zp[c * NB + bb];
                float y0 = xc[bb], y1 = xc[NB + bb];
                out[(size_t)t * TRAJ + bb]      = y0;
                out[(size_t)t * TRAJ + NB + bb] = y1;
                out[CONBASE + (size_t)t * NB + bb] = bm1 * z2;
                xn[bb]      = a0 * y0 + a1 * y1 + bm0 * z2;
                xn[NB + bb] = a2 * y0 + a3 * y1 + bm1 * z2;
            }
        }
    }
    __syncthreads();

    const char* gAh = (const char*)(g_Wh + (size_t)m0 * N);
    const char* gAl = (const char*)(g_Wl + (size_t)m0 * N);
    const char* gBh = (const char*)(hh + (size_t)b0t * N);
    const char* gBl = (const char*)(hl + (size_t)b0t * N);

    auto issue = [&](int ks) {
        int s = ks % STAGES;
        uint32_t stb = sb + HDR + s * STAGEB;
        size_t kb = (size_t)ks * (BK * 2);
#pragma unroll
        for (int it = 0; it < 2; ++it) {
            int idx = it * 256 + tid;
            int row = idx >> 2, chunk = idx & 3;
            uint32_t so = (uint32_t)(row * ROWB + chunk * 16);
            size_t go = (size_t)row * (N * 2) + kb + chunk * 16;
            cp16(stb + OFF_AH + so, gAh + go);
            cp16(stb + OFF_AL + so, gAl + go);
        }
        {
            int row = tid >> 2, chunk = tid & 3;
            uint32_t so = (uint32_t)(row * ROWB + chunk * 16);
            size_t go = (size_t)row * (N * 2) + kb + chunk * 16;
            cp16(stb + OFF_BH + so, gBh + go);
            cp16(stb + OFF_BL + so, gBl + go);
        }
    };

    issue(0); CPCOMMIT();
    issue(1); CPCOMMIT();

    float acc[2][4][4];
#pragma unroll
    for (int mi = 0; mi < 2; ++mi)
#pragma unroll
        for (int ni = 0; ni < 4; ++ni)
#pragma unroll
            for (int r = 0; r < 4; ++r) acc[mi][ni][r] = 0.0f;

    const int lr = lane & 7;
    const int g  = lane >> 3;
    const uint32_t aoff = (uint32_t)((wm * 32 + (g & 1) * 8 + lr) * ROWB + (g >> 1) * 16);
    const uint32_t boff = (uint32_t)((wn * 32 + (g >> 1) * 8 + lr) * ROWB + (g & 1) * 16);

    for (int ks = 0; ks < KSTEPS; ++ks) {
        CPWAIT1();
        __syncthreads();
        if (ks + 2 < KSTEPS) issue(ks + 2);
        CPCOMMIT();

        const uint32_t stb = sb + HDR + (ks % STAGES) * STAGEB;
        const uint32_t pAh = stb + OFF_AH + aoff;
        const uint32_t pAl = stb + OFF_AL + aoff;
        const uint32_t pBh = stb + OFF_BH + boff;
        const uint32_t pBl = stb + OFF_BL + boff;

#pragma unroll
        for (int kh = 0; kh < 2; ++kh) {
            const uint32_t khb = kh * 32;

            uint32_t bh[4][2], bl[4][2];
#pragma unroll
            for (int p = 0; p < 2; ++p) {
                LDSM4(bh[2*p][0], bh[2*p][1], bh[2*p+1][0], bh[2*p+1][1],
                      pBh + p * (16 * ROWB) + khb);
                LDSM4(bl[2*p][0], bl[2*p][1], bl[2*p+1][0], bl[2*p+1][1],
                      pBl + p * (16 * ROWB) + khb);
            }
            uint32_t ah[2][4], al[2][4];
#pragma unroll
            for (int mi = 0; mi < 2; ++mi) {
                LDSM4(ah[mi][0], ah[mi][1], ah[mi][2], ah[mi][3],
                      pAh + mi * (16 * ROWB) + khb);
                LDSM4(al[mi][0], al[mi][1], al[mi][2], al[mi][3],
                      pAl + mi * (16 * ROWB) + khb);
            }

#pragma unroll
            for (int mi = 0; mi < 2; ++mi)
#pragma unroll
                for (int ni = 0; ni < 4; ++ni)
                    MMA(acc[mi][ni], ah[mi][0], ah[mi][1], ah[mi][2], ah[mi][3],
                        bh[ni][0], bh[ni][1]);
#pragma unroll
            for (int mi = 0; mi < 2; ++mi)
#pragma unroll
                for (int ni = 0; ni < 4; ++ni)
                    MMA(acc[mi][ni], ah[mi][0], ah[mi][1], ah[mi][2], ah[mi][3],
                        bl[ni][0], bl[ni][1]);
#pragma unroll
            for (int mi = 0; mi < 2; ++mi)
#pragma unroll
                for (int ni = 0; ni < 4; ++ni)
                    MMA(acc[mi][ni], al[mi][0], al[mi][1], al[mi][2], al[mi][3],
                        bh[ni][0], bh[ni][1]);
        }
    }
    CPWAIT0();
    __syncthreads();

    // ---- Phase A: acc + M[i]*cax[b] -> Cs ----
    float* Cs = reinterpret_cast<float*>(smem + HDR);
#pragma unroll
    for (int mi = 0; mi < 2; ++mi) {
#pragma unroll
        for (int ni = 0; ni < 4; ++ni) {
            int row = wm * 32 + mi * 16 + (lane >> 2);
            int col = wn * 32 + ni * 8 + (lane & 3) * 2;
            float* c = acc[mi][ni];
            float2 v0 = make_float2(c[0] + m_s[row] * cax_s[col],
                                    c[1] + m_s[row] * cax_s[col + 1]);
            float2 v1 = make_float2(c[2] + m_s[row + 8] * cax_s[col],
                                    c[3] + m_s[row + 8] * cax_s[col + 1]);
            *reinterpret_cast<float2*>(&Cs[row * CSTRIDE + col]) = v0;
            *reinterpret_cast<float2*>(&Cs[(row + 8) * CSTRIDE + col]) = v1;
        }
    }
    __syncthreads();

    // ---- Phase B: traj_{t+1} h rows ----
    {
        int row = tid >> 1;
        int cb = (tid & 1) * 32;
        const float* src = Cs + row * CSTRIDE + cb;
        float* dst = out + (size_t)(t + 1) * TRAJ + (size_t)(2 + m0 + row) * NB + b0t + cb;
#pragma unroll
        for (int j = 0; j < 32; j += 4)
            *reinterpret_cast<float4*>(dst + j) = *reinterpret_cast<const float4*>(src + j);
    }

    // ---- Phase C: transposed fp16 split + Z·h partials (conflict-free b=tid&63) ----
    {
        int b = tid & 63;
        int q = tid >> 6;        // 0..3
        int rb = q * 32;
        size_t base = (size_t)(b0t + b) * N + m0 + rb;
        uint32_t* ohp = reinterpret_cast<uint32_t*>(oh + base);
        uint32_t* olp = reinterpret_cast<uint32_t*>(ol + base);
        float zh = 0.0f;
#pragma unroll
        for (int r = 0; r < 32; r += 2) {
            float v0 = Cs[(rb + r) * CSTRIDE + b];
            float v1 = Cs[(rb + r + 1) * CSTRIDE + b];
            zh += z_s[rb + r] * v0 + z_s[rb + r + 1] * v1;
            __half h0v = __float2half(v0);
            __half h1v = __float2half(v1);
            __half l0 = __float2half(v0 - __half2float(h0v));
            __half l1 = __float2half(v1 - __half2float(h1v));
            ohp[r >> 1] = (uint32_t)__half_as_ushort(h0v)
                        | ((uint32_t)__half_as_ushort(h1v) << 16);
            olp[r >> 1] = (uint32_t)__half_as_ushort(l0)
                        | ((uint32_t)__half_as_ushort(l1) << 16);
        }
        g_zp[nxt][(mt * 4 + q) * NB + b0t + b] = zh;
    }
}

// ---------------- launch ----------------
extern "C" void kernel_launch(void* const* d_in, const int* in_sizes, int n_in,
                              void* d_out, int out_size)
{
    const float* x0 = (const float*)d_in[0];
    const float* x1 = (const float*)d_in[1];
    const float* h0 = (const float*)d_in[2];
    const float* A  = (const float*)d_in[3];
    const float* Bm = (const float*)d_in[4];
    const float* C  = (const float*)d_in[5];
    const float* M  = (const float*)d_in[6];
    const float* Z  = (const float*)d_in[7];
    const float* U  = (const float*)d_in[8];
    const float* V  = (const float*)d_in[9];
    const float* W  = (const float*)d_in[10];
    (void)in_sizes; (void)n_in; (void)out_size;
    float* out = (float*)d_out;

    cudaFuncSetAttribute(gemm_step, cudaFuncAttributeMaxDynamicSharedMemorySize, SMEMSZ);

    build_wp<<<dim3(N / 256, N), 256>>>(W, M, Z, U, V, Bm, C);
    init_h<<<dim3(N / 32, NB / 32), dim3(32, 8)>>>(h0, out);
    init_zx<<<dim3(128, 4), 128>>>(h0, Z, x0, x1);

    for (int t = 0; t < NSTEPS - 1; ++t)
        gemm_step<<<dim3(NB / BN, N / BM), 256, SMEMSZ>>>(t & 1, A, Bm, C, M, Z, out, t);

    final_xcon<<<1, 512>>>(Bm, out);
}